// round 15
// baseline (speedup 1.0000x reference)
#include <cuda_runtime.h>
#include <cuda_fp16.h>
#include <cstdint>
#include <math.h>

#define Bsz   2
#define Seq   2048
#define Dim   1024
#define NHead 16
#define HDim  64

// fp16 operands
__device__ __half g_X [4096 * 1024];
__device__ __half g_Wq[3072 * 1024];
__device__ __half g_Wo[1024 * 1024];
// per-(b,h) planes [32][2048][64]
__device__ __half g_Q[32 * 2048 * 64];
__device__ __half g_K[32 * 2048 * 64];
__device__ __half g_V[32 * 2048 * 64];
// attention output fp16
__device__ __half g_Y[4096 * 1024];

// ===========================================================================
// helpers
// ===========================================================================
__device__ __forceinline__ void ldm_x4(uint32_t* r, uint32_t addr) {
    asm volatile("ldmatrix.sync.aligned.m8n8.x4.shared.b16 {%0,%1,%2,%3}, [%4];"
                 : "=r"(r[0]), "=r"(r[1]), "=r"(r[2]), "=r"(r[3]) : "r"(addr));
}
__device__ __forceinline__ void ldm_x4_t(uint32_t* r, uint32_t addr) {
    asm volatile("ldmatrix.sync.aligned.m8n8.x4.trans.shared.b16 {%0,%1,%2,%3}, [%4];"
                 : "=r"(r[0]), "=r"(r[1]), "=r"(r[2]), "=r"(r[3]) : "r"(addr));
}
__device__ __forceinline__ void mma_fp16(float* d, const uint32_t* a,
                                         const uint32_t* b) {
    asm volatile(
        "mma.sync.aligned.m16n8k16.row.col.f32.f16.f16.f32 "
        "{%0,%1,%2,%3}, {%4,%5,%6,%7}, {%8,%9}, {%0,%1,%2,%3};"
        : "+f"(d[0]), "+f"(d[1]), "+f"(d[2]), "+f"(d[3])
        : "r"(a[0]), "r"(a[1]), "r"(a[2]), "r"(a[3]), "r"(b[0]), "r"(b[1]));
}
__device__ __forceinline__ uint32_t smem_u32(const void* p) {
    uint32_t a;
    asm("{ .reg .u64 t; cvta.to.shared.u64 t, %1; cvt.u32.u64 %0, t; }"
        : "=r"(a) : "l"(p));
    return a;
}
__device__ __forceinline__ uint32_t pk_h2(__half a, __half b) {
    __half2 t(a, b);
    return *reinterpret_cast<uint32_t*>(&t);
}
__device__ __forceinline__ void cpa16(uint32_t s, const void* g) {
    asm volatile("cp.async.cg.shared.global [%0], [%1], 16;" :: "r"(s), "l"(g));
}
#define CP_COMMIT() asm volatile("cp.async.commit_group;")
#define CP_WAIT3()  asm volatile("cp.async.wait_group 3;")
#define CP_WAIT1()  asm volatile("cp.async.wait_group 1;")
#define CP_WAIT0()  asm volatile("cp.async.wait_group 0;")

// ===========================================================================
// fp32 -> fp16 convert (vectorized by 4)
// ===========================================================================
__global__ __launch_bounds__(256) void cvt_kernel(const float* __restrict__ src,
                                                  __half* __restrict__ dst,
                                                  int n4) {
    int i = blockIdx.x * blockDim.x + threadIdx.x;
    if (i >= n4) return;
    float4 v = ((const float4*)src)[i];
    ((uint2*)dst)[i] = make_uint2(
        pk_h2(__float2half(v.x), __float2half(v.y)),
        pk_h2(__float2half(v.z), __float2half(v.w)));
}

// ===========================================================================
// fused QKV epilogue store: rope on q/k, scale q, scatter to fp16 planes.
// ===========================================================================
__device__ __forceinline__ void qkv_store(int row, int col, float v0, float v1,
                                          const float* __restrict__ fc) {
    int b = row >> 11, s = row & 2047;
    int sec = col >> 10;            // 0=q, 1=k, 2=v
    int cm  = col & 1023;
    int h = cm >> 6, dd = cm & 63;
    size_t o = ((size_t)(b * NHead + h) * Seq + s) * HDim + dd;
    if (sec == 2) {
        *(uint32_t*)(g_V + o) = pk_h2(__float2half(v0), __float2half(v1));
    } else {
        int j = dd >> 1;
        float c  = fc[s * 64 + j * 2 + 0];
        float sn = fc[s * 64 + j * 2 + 1];
        float r0 = v0 * c - v1 * sn;
        float r1 = v1 * c + v0 * sn;
        if (sec == 0) {
            r0 *= 0.125f; r1 *= 0.125f;
            *(uint32_t*)(g_Q + o) = pk_h2(__float2half(r0), __float2half(r1));
        } else {
            *(uint32_t*)(g_K + o) = pk_h2(__float2half(r0), __float2half(r1));
        }
    }
}

// ===========================================================================
// gemm_h: C[M][N] = A[M][1024] @ B[N][1024]^T, fp16 operands, fp32 accum.
// mode 0: store fp32 C.  mode 1: fused rope+scatter (QKV).
// 128x128 tile, BK=64, 256 threads, 2-stage cp.async double buffer.
// ===========================================================================
#define LDSS 72
#define G_ARR (128 * LDSS * 2)       // 18432 B (fp16, 128 rows x 64 cols +pad)
#define G_STAGE (2 * G_ARR)          // 36864 B
#define GEMM_SMEM (2 * G_STAGE)      // 73728 B
#define GOA 0
#define GOB G_ARR
#define G_NIT 16

__device__ __forceinline__ void gemm_issue(
    int it, uint32_t sb, int bm, int bn, int row, int c0,
    const __half* A, const __half* B) {
    if (it < G_NIT) {
        uint32_t st = sb + (it & 1) * G_STAGE;
        int k0 = it * 64;
        size_t ga = (size_t)(bm + row) * 1024 + k0 + c0;
        size_t gb = (size_t)(bn + row) * 1024 + k0 + c0;
        uint32_t so = row * (LDSS * 2) + c0 * 2;
#pragma unroll
        for (int ci = 0; ci < 4; ci++) {
            cpa16(st + GOA + so + ci * 16, A + ga + ci * 8);
            cpa16(st + GOB + so + ci * 16, B + gb + ci * 8);
        }
    }
    CP_COMMIT();
}

__global__ __launch_bounds__(256) void gemm_h(
    const __half* __restrict__ A, const __half* __restrict__ B,
    float* __restrict__ C, int N, const float* __restrict__ fc, int mode) {
    extern __shared__ char smem[];
    const uint32_t sb = smem_u32(smem);
    const int t = threadIdx.x, lane = t & 31, wid = t >> 5;
    const int wm = (wid & 1) * 64, wn = (wid >> 1) * 32;
    const int bm = blockIdx.y * 128, bn = blockIdx.x * 128;
    const int row = t >> 1, c0 = (t & 1) * 32;

    float d[4][4][4];
#pragma unroll
    for (int mi = 0; mi < 4; mi++)
#pragma unroll
        for (int nj = 0; nj < 4; nj++)
#pragma unroll
            for (int e = 0; e < 4; e++) d[mi][nj][e] = 0.f;

    gemm_issue(0, sb, bm, bn, row, c0, A, B);
    gemm_issue(1, sb, bm, bn, row, c0, A, B);

    for (int it = 0; it < G_NIT; it++) {
        CP_WAIT1();
        __syncthreads();
        const uint32_t st = sb + (it & 1) * G_STAGE;
#pragma unroll
        for (int ks = 0; ks < 4; ks++) {
            const int k0 = ks * 16;
            uint32_t af[4][4];
            const int arow = wm + (lane & 15);
            const int acol = k0 + ((lane & 16) ? 8 : 0);
#pragma unroll
            for (int mi = 0; mi < 4; mi++)
                ldm_x4(af[mi], st + GOA +
                       (uint32_t)(((arow + mi * 16) * LDSS + acol) * 2));
            uint32_t bf[2][4];
            const int brow = wn + (lane & 7) + ((lane & 16) >> 1);
            const int bcol = k0 + ((lane & 8) ? 8 : 0);
#pragma unroll
            for (int nb = 0; nb < 2; nb++)
                ldm_x4(bf[nb], st + GOB +
                       (uint32_t)(((brow + nb * 16) * LDSS + bcol) * 2));
#pragma unroll
            for (int mi = 0; mi < 4; mi++)
#pragma unroll
                for (int nj = 0; nj < 4; nj++)
                    mma_fp16(d[mi][nj], af[mi], &bf[nj >> 1][(nj & 1) * 2]);
        }
        __syncthreads();
        gemm_issue(it + 2, sb, bm, bn, row, c0, A, B);
    }

    if (mode == 0) {
#pragma unroll
        for (int mi = 0; mi < 4; mi++)
#pragma unroll
            for (int nj = 0; nj < 4; nj++) {
                int r = bm + wm + mi * 16 + (lane >> 2);
                int c = bn + wn + nj * 8 + (lane & 3) * 2;
                *(float2*)&C[(size_t)r * N + c] =
                    make_float2(d[mi][nj][0], d[mi][nj][1]);
                *(float2*)&C[(size_t)(r + 8) * N + c] =
                    make_float2(d[mi][nj][2], d[mi][nj][3]);
            }
    } else {
#pragma unroll
        for (int mi = 0; mi < 4; mi++)
#pragma unroll
            for (int nj = 0; nj < 4; nj++) {
                int r = bm + wm + mi * 16 + (lane >> 2);
                int c = bn + wn + nj * 8 + (lane & 3) * 2;
                qkv_store(r,     c, d[mi][nj][0], d[mi][nj][1], fc);
                qkv_store(r + 8, c, d[mi][nj][2], d[mi][nj][3], fc);
            }
    }
}

// ===========================================================================
// attention: 128 q-rows x (b,h); k-tile 64; 4-stage cp.async; 2 CTAs/SM;
// fp16 HMMA; V row-major + ldmatrix.trans; online softmax.
// ===========================================================================
#define LDKV 72
#define A_K (64 * LDKV * 2)          // 9216 B
#define A_STAGE (2 * A_K)            // 18432 B (K + V)
#define ATTN_SMEM (4 * A_STAGE)      // 73728 B
#define AK 0
#define AV A_K

__device__ __forceinline__ void attn_issue(int kt, int nkt, uint32_t sb,
                                           size_t base, int row4, int j2) {
    if (kt < nkt) {
        uint32_t st = sb + (kt & 3) * A_STAGE;
        size_t g = base + (size_t)(kt * 64 + row4) * 64 + j2 * 16;
        uint32_t so = row4 * (LDKV * 2) + j2 * 32;
        cpa16(st + AK + so,      g_K + g);
        cpa16(st + AK + so + 16, g_K + g + 8);
        cpa16(st + AV + so,      g_V + g);
        cpa16(st + AV + so + 16, g_V + g + 8);
    }
    CP_COMMIT();
}

__global__ __launch_bounds__(256, 2) void attn_h() {
    extern __shared__ char smc[];
    const uint32_t sb = smem_u32(smc);
    const int tid = threadIdx.x, lane = tid & 31, w = tid >> 5;
    const int qt = (int)gridDim.x - 1 - (int)blockIdx.x;   // heavy tiles first
    const int bh = blockIdx.y;
    const int b = bh >> 4, h = bh & 15;
    const size_t base = (size_t)bh * Seq * HDim;
    const int q0w = w * 16;
    const int nkt = 2 * (qt + 1);
    const int row4 = tid >> 2, j2 = tid & 3;

    const int la_r = lane & 15;
    const int la_c = (lane & 16) ? 8 : 0;
    const int lb_r = (lane & 7) + ((lane & 16) >> 1);
    const int lb_c = (lane & 8) ? 8 : 0;

    // ---- stage Q (128 rows) into stage-0 region, extract frags ----
    {
        int row2 = tid >> 1, j1 = tid & 1;
        size_t gq = base + (size_t)(qt * 128 + row2) * 64 + j1 * 32;
        uint32_t so = row2 * (LDKV * 2) + j1 * 64;
#pragma unroll
        for (int c = 0; c < 4; c++)
            cpa16(sb + so + c * 16, g_Q + gq + c * 8);
    }
    CP_COMMIT();
    CP_WAIT0();
    __syncthreads();
    uint32_t qf[4][4];
#pragma unroll
    for (int ks = 0; ks < 4; ks++)
        ldm_x4(qf[ks], sb +
               (uint32_t)(((q0w + la_r) * LDKV + ks * 16 + la_c) * 2));
    __syncthreads();

    float accO[8][4];
#pragma unroll
    for (int i = 0; i < 8; i++)
#pragma unroll
        for (int e = 0; e < 4; e++) accO[i][e] = 0.f;
    float m0 = -1e30f, m1 = -1e30f, l0 = 0.f, l1 = 0.f;

    attn_issue(0, nkt, sb, base, row4, j2);
    attn_issue(1, nkt, sb, base, row4, j2);
    attn_issue(2, nkt, sb, base, row4, j2);
    attn_issue(3, nkt, sb, base, row4, j2);

    const int r0 = qt * 128 + q0w + (lane >> 2), r1 = r0 + 8;

    for (int kt = 0; kt < nkt; kt++) {
        CP_WAIT3();
        __syncthreads();
        const uint32_t st = sb + (kt & 3) * A_STAGE;

        // ---- S = Q K^T (64 cols) ----
        float sa[8][4];
#pragma unroll
        for (int i = 0; i < 8; i++)
#pragma unroll
            for (int e = 0; e < 4; e++) sa[i][e] = 0.f;

#pragma unroll
        for (int ks = 0; ks < 4; ks++) {
#pragma unroll
            for (int bg = 0; bg < 4; bg++) {
                uint32_t kf[4];
                ldm_x4(kf, st + AK +
                       (uint32_t)(((bg * 16 + lb_r) * LDKV + ks * 16 + lb_c) * 2));
                mma_fp16(sa[2 * bg],     qf[ks], kf);
                mma_fp16(sa[2 * bg + 1], qf[ks], kf + 2);
            }
        }

        // ---- causal mask (only tiles overlapping the diagonal) ----
        if (kt >= 2 * qt) {
            const int kb = kt * 64;
#pragma unroll
            for (int nt = 0; nt < 8; nt++) {
                int c = kb + nt * 8 + (lane & 3) * 2;
                if (c > r0)     sa[nt][0] = -1e30f;
                if (c + 1 > r0) sa[nt][1] = -1e30f;
                if (c > r1)     sa[nt][2] = -1e30f;
                if (c + 1 > r1) sa[nt][3] = -1e30f;
            }
        }

        // ---- online softmax ----
        float mx0 = -1e30f, mx1 = -1e30f;
#pragma unroll
        for (int nt = 0; nt < 8; nt++) {
            mx0 = fmaxf(mx0, fmaxf(sa[nt][0], sa[nt][1]));
            mx1 = fmaxf(mx1, fmaxf(sa[nt][2], sa[nt][3]));
        }
        mx0 = fmaxf(mx0, __shfl_xor_sync(0xffffffffu, mx0, 1));
        mx0 = fmaxf(mx0, __shfl_xor_sync(0xffffffffu, mx0, 2));
        mx1 = fmaxf(mx1, __shfl_xor_sync(0xffffffffu, mx1, 1));
        mx1 = fmaxf(mx1, __shfl_xor_sync(0xffffffffu, mx1, 2));

        float nm0 = fmaxf(m0, mx0), nm1 = fmaxf(m1, mx1);
        float c0 = __expf(m0 - nm0), c1 = __expf(m1 - nm1);
        m0 = nm0; m1 = nm1;

        float rs0 = 0.f, rs1 = 0.f;
#pragma unroll
        for (int nt = 0; nt < 8; nt++) {
            sa[nt][0] = __expf(sa[nt][0] - m0);
            sa[nt][1] = __expf(sa[nt][1] - m0);
            sa[nt][2] = __expf(sa[nt][2] - m1);
            sa[nt][3] = __expf(sa[nt][3] - m1);
            rs0 += sa[nt][0] + sa[nt][1];
            rs1 += sa[nt][2] + sa[nt][3];
        }
        rs0 += __shfl_xor_sync(0xffffffffu, rs0, 1);
        rs0 += __shfl_xor_sync(0xffffffffu, rs0, 2);
        rs1 += __shfl_xor_sync(0xffffffffu, rs1, 1);
        rs1 += __shfl_xor_sync(0xffffffffu, rs1, 2);
        l0 = l0 * c0 + rs0;
        l1 = l1 * c1 + rs1;
#pragma unroll
        for (int dt = 0; dt < 8; dt++) {
            accO[dt][0] *= c0; accO[dt][1] *= c0;
            accO[dt][2] *= c1; accO[dt][3] *= c1;
        }

        // ---- O += P V (V via trans ldmatrix) ----
#pragma unroll
        for (int ks = 0; ks < 4; ks++) {
            uint32_t pa[4];
#pragma unroll
            for (int hf = 0; hf < 2; hf++) {
                const float* s4 = sa[2 * ks + hf];
                pa[2 * hf + 0] = pk_h2(__float2half(s4[0]), __float2half(s4[1]));
                pa[2 * hf + 1] = pk_h2(__float2half(s4[2]), __float2half(s4[3]));
            }
#pragma unroll
            for (int vg = 0; vg < 4; vg++) {
                uint32_t vf[4];
                ldm_x4_t(vf, st + AV +
                         (uint32_t)(((ks * 16 + la_r) * LDKV + vg * 16 + la_c) * 2));
                mma_fp16(accO[2 * vg],     pa, vf);
                mma_fp16(accO[2 * vg + 1], pa, vf + 2);
            }
        }
        __syncthreads();
        attn_issue(kt + 4, nkt, sb, base, row4, j2);
    }

    // ---- write Y (fp16) ----
    const float il0 = 1.f / l0, il1 = 1.f / l1;
    const int row0 = qt * 128 + q0w + (lane >> 2);
    const int row1 = row0 + 8;
#pragma unroll
    for (int dt = 0; dt < 8; dt++) {
        int col = h * HDim + dt * 8 + (lane & 3) * 2;
        size_t i0 = (size_t)(b * Seq + row0) * Dim + col;
        size_t i1 = (size_t)(b * Seq + row1) * Dim + col;
        *(uint32_t*)&g_Y[i0] = pk_h2(__float2half(accO[dt][0] * il0),
                                     __float2half(accO[dt][1] * il0));
        *(uint32_t*)&g_Y[i1] = pk_h2(__float2half(accO[dt][2] * il1),
                                     __float2half(accO[dt][3] * il1));
    }
}

// ===========================================================================
extern "C" void kernel_launch(void* const* d_in, const int* in_sizes, int n_in,
                              void* d_out, int out_size) {
    const float* x    = (const float*)d_in[0];
    const float* fc   = (const float*)d_in[1];
    // d_in[2] = mask — causality structural, unused
    const float* wqkv = (const float*)d_in[3];
    const float* wo   = (const float*)d_in[4];
    float* out = (float*)d_out;

    __half *X, *Wq, *Wo_, *Y;
    cudaGetSymbolAddress((void**)&X,   g_X);
    cudaGetSymbolAddress((void**)&Wq,  g_Wq);
    cudaGetSymbolAddress((void**)&Wo_, g_Wo);
    cudaGetSymbolAddress((void**)&Y,   g_Y);

    cudaFuncSetAttribute(gemm_h, cudaFuncAttributeMaxDynamicSharedMemorySize,
                         GEMM_SMEM);
    cudaFuncSetAttribute(attn_h, cudaFuncAttributeMaxDynamicSharedMemorySize,
                         ATTN_SMEM);

    const int M = Bsz * Seq;  // 4096

    // 0) convert inputs to fp16
    cvt_kernel<<<(M * Dim / 4 + 255) / 256, 256>>>(x, X, M * Dim / 4);
    cvt_kernel<<<(3 * Dim * Dim / 4 + 255) / 256, 256>>>(wqkv, Wq,
                                                         3 * Dim * Dim / 4);
    cvt_kernel<<<(Dim * Dim / 4 + 255) / 256, 256>>>(wo, Wo_, Dim * Dim / 4);
    // 1) QKV gemm with fused rope + plane scatter
    {
        dim3 grid(3 * Dim / 128, M / 128);
        gemm_h<<<grid, 256, GEMM_SMEM>>>(X, Wq, out /*unused*/, 3 * Dim, fc, 1);
    }
    // 2) attention -> Y (fp16)
    {
        dim3 grid(Seq / 128, Bsz * NHead);
        attn_h<<<grid, 256, ATTN_SMEM>>>();
    }
    // 3) out = Y @ Wo^T
    {
        dim3 grid(Dim / 128, M / 128);
        gemm_h<<<grid, 256, GEMM_SMEM>>>(Y, Wo_, out, Dim, nullptr, 0);
    }
}